// round 13
// baseline (speedup 1.0000x reference)
#include <cuda_runtime.h>
#include <math.h>

// Problem constants (fixed shapes from reference):
//   label    [4,1024,1024] int32, features [4,256,256,256] fp32
#define NN   4
#define KC   19
#define PP   65536          // 256*256 downsampled pixels per image
#define VV   131            // 10000 / 76
#define TT   (NN*KC)        // 76
#define MM   (TT*VV)        // 9956 total feature rows
#define CC   256
#define POS  (NN*VV)        // 524 same-class rows (incl. self)
#define TILE 64
#define NT   ((MM + TILE - 1) / TILE)   // 156

// Static scratch (no allocations allowed). Fully rewritten every launch.
__device__ int    g_idx[TT * VV];       // selected pixel per (t, v)
__device__ float  g_F[MM * CC];         // normalized features, row-major
__device__ float  g_pos[MM * POS];      // positive logits per row
__device__ float  g_negsum[MM];         // sum exp(logit) over different-class cols
__device__ double g_acc;                // loss accumulator

__global__ void init_kernel() {
    int i = blockIdx.x * blockDim.x + threadIdx.x;
    if (i < MM) g_negsum[i] = 0.0f;
    if (i == 0) g_acc = 0.0;
}

// One block per (image, class): ordered compaction of the first VV pixels
// (raster order over the ::4,::4 downsample) whose label == class.
__global__ void select_kernel(const int* __restrict__ label) {
    int b = blockIdx.x;
    int n = b / KC, k = b % KC;
    const int* lab = label + (size_t)n * 1024 * 1024;
    __shared__ int s_count;
    __shared__ int warp_cnt[8];
    if (threadIdx.x == 0) s_count = 0;
    __syncthreads();
    for (int chunk = 0; chunk < PP; chunk += 256) {
        int p = chunk + threadIdx.x;                    // downsampled pixel index
        int lv = lab[(p >> 8) * 4096 + (p & 255) * 4];  // label[n, 4*i, 4*j]
        bool m = (lv == k);
        unsigned bal = __ballot_sync(0xffffffffu, m);
        int lane = threadIdx.x & 31, wid = threadIdx.x >> 5;
        int rank = __popc(bal & ((1u << lane) - 1));
        if (lane == 0) warp_cnt[wid] = __popc(bal);
        __syncthreads();
        int off = 0, total = 0;
#pragma unroll
        for (int w = 0; w < 8; w++) {
            int cw = warp_cnt[w];
            if (w < wid) off += cw;
            total += cw;
        }
        int base = s_count;
        int pos = base + off + rank;
        if (m && pos < VV) g_idx[b * VV + pos] = p;
        __syncthreads();
        if (threadIdx.x == 0) s_count = base + total;
        __syncthreads();
        if (base + total >= VV) break;                  // uniform across block
    }
}

// One block per output row: gather the 256-dim feature vector for its pixel
// and L2-normalize (matching F.normalize semantics: / max(||x||, 1e-12)).
__global__ void gather_kernel(const float* __restrict__ features) {
    int m = blockIdx.x;
    int t = m / VV, v = m - t * VV;
    int n = t / KC;
    int pix = g_idx[t * VV + v];
    int c = threadIdx.x;
    float val = features[((size_t)(n * CC + c)) * PP + pix];
    float ss = val * val;
#pragma unroll
    for (int o = 16; o; o >>= 1) ss += __shfl_xor_sync(0xffffffffu, ss, o);
    __shared__ float ws[8];
    if ((c & 31) == 0) ws[c >> 5] = ss;
    __syncthreads();
    float s = 0.0f;
#pragma unroll
    for (int w = 0; w < 8; w++) s += ws[w];
    float inv = 1.0f / fmaxf(sqrtf(s), 1e-12f);
    g_F[(size_t)m * CC + c] = val * inv;
}

// Fused Gram kernel: 64x64 tile per block, 4x4 per thread.
// Epilogue fuses logit scale (x2), exp, class routing:
//   same class  -> store logit to g_pos[i][slot(j)]
//   diff class  -> accumulate exp into negsum[i] (shuffle-reduce + atomic)
__global__ void __launch_bounds__(256) gemm_kernel() {
    __shared__ float As[16][TILE];
    __shared__ float Bs[16][TILE];
    __shared__ int s_ci[TILE];
    __shared__ int s_cj[TILE];
    __shared__ int s_slot[TILE];

    int i0 = blockIdx.y * TILE, j0 = blockIdx.x * TILE;
    int tx = threadIdx.x, ty = threadIdx.y;
    int tid = ty * 16 + tx;

    if (tid < TILE) {
        int i = i0 + tid;
        s_ci[tid] = (i < MM) ? (i / VV) % KC : -1;
    } else if (tid < 2 * TILE) {
        int jj = tid - TILE;
        int j = j0 + jj;
        if (j < MM) {
            int t = j / VV, v = j - t * VV;
            s_cj[jj] = t % KC;
            s_slot[jj] = (t / KC) * VV + v;   // image*131 + v  in [0,524)
        } else {
            s_cj[jj] = -2;
            s_slot[jj] = 0;
        }
    }

    float acc[4][4];
#pragma unroll
    for (int a = 0; a < 4; a++)
#pragma unroll
        for (int b = 0; b < 4; b++) acc[a][b] = 0.0f;

    for (int k0 = 0; k0 < CC; k0 += 16) {
#pragma unroll
        for (int r = 0; r < 4; r++) {
            int e = tid + 256 * r;
            int row = e >> 4, kk = e & 15;
            int gi = i0 + row;
            As[kk][row] = (gi < MM) ? g_F[(size_t)gi * CC + k0 + kk] : 0.0f;
            int gj = j0 + row;
            Bs[kk][row] = (gj < MM) ? g_F[(size_t)gj * CC + k0 + kk] : 0.0f;
        }
        __syncthreads();
#pragma unroll
        for (int kk = 0; kk < 16; kk++) {
            float4 av = *(const float4*)&As[kk][ty * 4];
            float4 bv = *(const float4*)&Bs[kk][tx * 4];
            float a4[4] = {av.x, av.y, av.z, av.w};
            float b4[4] = {bv.x, bv.y, bv.z, bv.w};
#pragma unroll
            for (int a = 0; a < 4; a++)
#pragma unroll
                for (int b = 0; b < 4; b++) acc[a][b] += a4[a] * b4[b];
        }
        __syncthreads();
    }

    float ns[4] = {0.0f, 0.0f, 0.0f, 0.0f};
#pragma unroll
    for (int a = 0; a < 4; a++) {
        int irow = ty * 4 + a;
        int i = i0 + irow;
        if (i >= MM) continue;
        int ci = s_ci[irow];
#pragma unroll
        for (int b = 0; b < 4; b++) {
            int jj = tx * 4 + b;
            int j = j0 + jj;
            if (j >= MM) continue;
            float g = 2.0f * acc[a][b];   // / TEMPERATURE = 0.5
            if (ci == s_cj[jj]) {
                g_pos[(size_t)i * POS + s_slot[jj]] = g;
            } else {
                ns[a] += __expf(g);
            }
        }
    }
    // reduce the 4 per-row partials across the 16 tx lanes (same-ty half-warps)
#pragma unroll
    for (int a = 0; a < 4; a++) {
        float vsum = ns[a];
#pragma unroll
        for (int o = 8; o; o >>= 1) vsum += __shfl_down_sync(0xffffffffu, vsum, o, 16);
        if (tx == 0) {
            int i = i0 + ty * 4 + a;
            if (i < MM && vsum != 0.0f) atomicAdd(&g_negsum[i], vsum);
        }
    }
}

// Per-row pass over the 524 positive logits:
//   mean over j!=i of (L - log(exp(L) + negsum[i])), divided by 523.
__global__ void row_loss_kernel() {
    int i = blockIdx.x;
    int t = i / VV, v = i - t * VV;
    int diag = (t / KC) * VV + v;
    float nsv = g_negsum[i];
    float lsum = 0.0f;
    for (int s = threadIdx.x; s < POS; s += blockDim.x) {
        if (s == diag) continue;
        float L = g_pos[(size_t)i * POS + s];
        lsum += L - __logf(__expf(L) + nsv);
    }
#pragma unroll
    for (int o = 16; o; o >>= 1) lsum += __shfl_xor_sync(0xffffffffu, lsum, o);
    __shared__ float ws[8];
    if ((threadIdx.x & 31) == 0) ws[threadIdx.x >> 5] = lsum;
    __syncthreads();
    if (threadIdx.x == 0) {
        float s = 0.0f;
#pragma unroll
        for (int w = 0; w < 8; w++) s += ws[w];
        atomicAdd(&g_acc, (double)(s / 523.0f));
    }
}

__global__ void final_kernel(float* __restrict__ out) {
    out[0] = (float)(-g_acc / (double)MM);
}

extern "C" void kernel_launch(void* const* d_in, const int* in_sizes, int n_in,
                              void* d_out, int out_size) {
    const int* label;
    const float* features;
    // label has 4*1024*1024 = 4194304 elements; features 4*256*65536 = 67108864.
    if (in_sizes[0] == 4 * 1024 * 1024) {
        label = (const int*)d_in[0];
        features = (const float*)d_in[1];
    } else {
        label = (const int*)d_in[1];
        features = (const float*)d_in[0];
    }

    init_kernel<<<(MM + 1023) / 1024, 1024>>>();
    select_kernel<<<TT, 256>>>(label);
    gather_kernel<<<MM, 256>>>(features);
    dim3 grid(NT, NT), blk(16, 16);
    gemm_kernel<<<grid, blk>>>();
    row_loss_kernel<<<MM, 256>>>();
    final_kernel<<<1, 1>>>((float*)d_out);
}

// round 14
// speedup vs baseline: 1.0006x; 1.0006x over previous
#include <cuda_runtime.h>
#include <math.h>

// Problem constants (fixed shapes from reference):
//   label    [4,1024,1024] int32, features [4,256,256,256] fp32
#define NN   4
#define KC   19
#define PP   65536          // 256*256 downsampled pixels per image
#define VV   131            // 10000 / 76
#define TT   (NN*KC)        // 76
#define MM   (TT*VV)        // 9956 total feature rows
#define CC   256
#define POS  (NN*VV)        // 524 same-class rows (incl. self)
#define TILE 64
#define NT   ((MM + TILE - 1) / TILE)   // 156

// Static scratch (no allocations allowed). Fully rewritten every launch.
__device__ int    g_idx[TT * VV];       // selected pixel per (t, v)
__device__ float  g_F[MM * CC];         // normalized features, row-major
__device__ float  g_pos[MM * POS];      // positive logits per row
__device__ float  g_negsum[MM];         // sum exp(logit) over different-class cols
__device__ double g_acc;                // loss accumulator

__global__ void init_kernel() {
    int i = blockIdx.x * blockDim.x + threadIdx.x;
    if (i < MM) g_negsum[i] = 0.0f;
    if (i == 0) g_acc = 0.0;
}

// One block per (image, class): ordered compaction of the first VV pixels
// (raster order over the ::4,::4 downsample) whose label == class.
__global__ void select_kernel(const int* __restrict__ label) {
    int b = blockIdx.x;
    int n = b / KC, k = b % KC;
    const int* lab = label + (size_t)n * 1024 * 1024;
    __shared__ int s_count;
    __shared__ int warp_cnt[8];
    if (threadIdx.x == 0) s_count = 0;
    __syncthreads();
    for (int chunk = 0; chunk < PP; chunk += 256) {
        int p = chunk + threadIdx.x;                    // downsampled pixel index
        int lv = lab[(p >> 8) * 4096 + (p & 255) * 4];  // label[n, 4*i, 4*j]
        bool m = (lv == k);
        unsigned bal = __ballot_sync(0xffffffffu, m);
        int lane = threadIdx.x & 31, wid = threadIdx.x >> 5;
        int rank = __popc(bal & ((1u << lane) - 1));
        if (lane == 0) warp_cnt[wid] = __popc(bal);
        __syncthreads();
        int off = 0, total = 0;
#pragma unroll
        for (int w = 0; w < 8; w++) {
            int cw = warp_cnt[w];
            if (w < wid) off += cw;
            total += cw;
        }
        int base = s_count;
        int pos = base + off + rank;
        if (m && pos < VV) g_idx[b * VV + pos] = p;
        __syncthreads();
        if (threadIdx.x == 0) s_count = base + total;
        __syncthreads();
        if (base + total >= VV) break;                  // uniform across block
    }
}

// One block per output row: gather the 256-dim feature vector for its pixel
// and L2-normalize (matching F.normalize semantics: / max(||x||, 1e-12)).
__global__ void gather_kernel(const float* __restrict__ features) {
    int m = blockIdx.x;
    int t = m / VV, v = m - t * VV;
    int n = t / KC;
    int pix = g_idx[t * VV + v];
    int c = threadIdx.x;
    float val = features[((size_t)(n * CC + c)) * PP + pix];
    float ss = val * val;
#pragma unroll
    for (int o = 16; o; o >>= 1) ss += __shfl_xor_sync(0xffffffffu, ss, o);
    __shared__ float ws[8];
    if ((c & 31) == 0) ws[c >> 5] = ss;
    __syncthreads();
    float s = 0.0f;
#pragma unroll
    for (int w = 0; w < 8; w++) s += ws[w];
    float inv = 1.0f / fmaxf(sqrtf(s), 1e-12f);
    g_F[(size_t)m * CC + c] = val * inv;
}

// Fused Gram kernel: 64x64 tile per block, 4x4 per thread.
// Epilogue fuses logit scale (x2), exp, class routing:
//   same class  -> store logit to g_pos[i][slot(j)]
//   diff class  -> accumulate exp into negsum[i] (shuffle-reduce + atomic)
__global__ void __launch_bounds__(256) gemm_kernel() {
    __shared__ float As[16][TILE];
    __shared__ float Bs[16][TILE];
    __shared__ int s_ci[TILE];
    __shared__ int s_cj[TILE];
    __shared__ int s_slot[TILE];

    int i0 = blockIdx.y * TILE, j0 = blockIdx.x * TILE;
    int tx = threadIdx.x, ty = threadIdx.y;
    int tid = ty * 16 + tx;

    if (tid < TILE) {
        int i = i0 + tid;
        s_ci[tid] = (i < MM) ? (i / VV) % KC : -1;
    } else if (tid < 2 * TILE) {
        int jj = tid - TILE;
        int j = j0 + jj;
        if (j < MM) {
            int t = j / VV, v = j - t * VV;
            s_cj[jj] = t % KC;
            s_slot[jj] = (t / KC) * VV + v;   // image*131 + v  in [0,524)
        } else {
            s_cj[jj] = -2;
            s_slot[jj] = 0;
        }
    }

    float acc[4][4];
#pragma unroll
    for (int a = 0; a < 4; a++)
#pragma unroll
        for (int b = 0; b < 4; b++) acc[a][b] = 0.0f;

    for (int k0 = 0; k0 < CC; k0 += 16) {
#pragma unroll
        for (int r = 0; r < 4; r++) {
            int e = tid + 256 * r;
            int row = e >> 4, kk = e & 15;
            int gi = i0 + row;
            As[kk][row] = (gi < MM) ? g_F[(size_t)gi * CC + k0 + kk] : 0.0f;
            int gj = j0 + row;
            Bs[kk][row] = (gj < MM) ? g_F[(size_t)gj * CC + k0 + kk] : 0.0f;
        }
        __syncthreads();
#pragma unroll
        for (int kk = 0; kk < 16; kk++) {
            float4 av = *(const float4*)&As[kk][ty * 4];
            float4 bv = *(const float4*)&Bs[kk][tx * 4];
            float a4[4] = {av.x, av.y, av.z, av.w};
            float b4[4] = {bv.x, bv.y, bv.z, bv.w};
#pragma unroll
            for (int a = 0; a < 4; a++)
#pragma unroll
                for (int b = 0; b < 4; b++) acc[a][b] += a4[a] * b4[b];
        }
        __syncthreads();
    }

    float ns[4] = {0.0f, 0.0f, 0.0f, 0.0f};
#pragma unroll
    for (int a = 0; a < 4; a++) {
        int irow = ty * 4 + a;
        int i = i0 + irow;
        if (i >= MM) continue;
        int ci = s_ci[irow];
#pragma unroll
        for (int b = 0; b < 4; b++) {
            int jj = tx * 4 + b;
            int j = j0 + jj;
            if (j >= MM) continue;
            float g = 2.0f * acc[a][b];   // / TEMPERATURE = 0.5
            if (ci == s_cj[jj]) {
                g_pos[(size_t)i * POS + s_slot[jj]] = g;
            } else {
                ns[a] += __expf(g);
            }
        }
    }
    // reduce the 4 per-row partials across the 16 tx lanes (same-ty half-warps)
#pragma unroll
    for (int a = 0; a < 4; a++) {
        float vsum = ns[a];
#pragma unroll
        for (int o = 8; o; o >>= 1) vsum += __shfl_down_sync(0xffffffffu, vsum, o, 16);
        if (tx == 0) {
            int i = i0 + ty * 4 + a;
            if (i < MM && vsum != 0.0f) atomicAdd(&g_negsum[i], vsum);
        }
    }
}

// Per-row pass over the 524 positive logits:
//   mean over j!=i of (L - log(exp(L) + negsum[i])), divided by 523.
__global__ void row_loss_kernel() {
    int i = blockIdx.x;
    int t = i / VV, v = i - t * VV;
    int diag = (t / KC) * VV + v;
    float nsv = g_negsum[i];
    float lsum = 0.0f;
    for (int s = threadIdx.x; s < POS; s += blockDim.x) {
        if (s == diag) continue;
        float L = g_pos[(size_t)i * POS + s];
        lsum += L - __logf(__expf(L) + nsv);
    }
#pragma unroll
    for (int o = 16; o; o >>= 1) lsum += __shfl_xor_sync(0xffffffffu, lsum, o);
    __shared__ float ws[8];
    if ((threadIdx.x & 31) == 0) ws[threadIdx.x >> 5] = lsum;
    __syncthreads();
    if (threadIdx.x == 0) {
        float s = 0.0f;
#pragma unroll
        for (int w = 0; w < 8; w++) s += ws[w];
        atomicAdd(&g_acc, (double)(s / 523.0f));
    }
}

__global__ void final_kernel(float* __restrict__ out) {
    out[0] = (float)(-g_acc / (double)MM);
}

extern "C" void kernel_launch(void* const* d_in, const int* in_sizes, int n_in,
                              void* d_out, int out_size) {
    const int* label;
    const float* features;
    // label has 4*1024*1024 = 4194304 elements; features 4*256*65536 = 67108864.
    if (in_sizes[0] == 4 * 1024 * 1024) {
        label = (const int*)d_in[0];
        features = (const float*)d_in[1];
    } else {
        label = (const int*)d_in[1];
        features = (const float*)d_in[0];
    }

    init_kernel<<<(MM + 1023) / 1024, 1024>>>();
    select_kernel<<<TT, 256>>>(label);
    gather_kernel<<<MM, 256>>>(features);
    dim3 grid(NT, NT), blk(16, 16);
    gemm_kernel<<<grid, blk>>>();
    row_loss_kernel<<<MM, 256>>>();
    final_kernel<<<1, 1>>>((float*)d_out);
}

// round 15
// speedup vs baseline: 3.3782x; 3.3763x over previous
#include <cuda_runtime.h>
#include <math.h>

// Problem constants (fixed shapes from reference):
//   label    [4,1024,1024] int32, features [4,256,256,256] fp32
#define NN   4
#define KC   19
#define PP   65536          // 256*256 downsampled pixels per image
#define VV   131            // 10000 / 76
#define TT   (NN*KC)        // 76
#define MM   (TT*VV)        // 9956 total feature rows
#define CC   256
#define POS  (NN*VV)        // 524 same-class rows (incl. self)

#define BT   128                         // block tile (i and j)
#define NTB  ((MM + BT - 1) / BT)        // 78
#define NBLK (NTB * (NTB + 1) / 2)       // 3081 upper-triangle tiles
#define KK   8                           // k-chunk

// Static scratch (no allocations allowed). Fully rewritten every launch.
__device__ int    g_idx[TT * VV];       // selected pixel per (t, v)
__device__ float  g_F[MM * CC];         // normalized features, row-major
__device__ float  g_pos[(size_t)MM * POS]; // positive logits per row
__device__ float  g_negsum[MM];         // sum exp(logit) over different-class cols
__device__ double g_acc;                // loss accumulator

__global__ void init_kernel() {
    int i = blockIdx.x * blockDim.x + threadIdx.x;
    if (i < MM) g_negsum[i] = 0.0f;
    if (i == 0) g_acc = 0.0;
}

// One block per (image, class): ordered compaction of the first VV pixels
// (raster order over the ::4,::4 downsample) whose label == class.
__global__ void select_kernel(const int* __restrict__ label) {
    int b = blockIdx.x;
    int n = b / KC, k = b % KC;
    const int* lab = label + (size_t)n * 1024 * 1024;
    __shared__ int s_count;
    __shared__ int warp_cnt[8];
    if (threadIdx.x == 0) s_count = 0;
    __syncthreads();
    for (int chunk = 0; chunk < PP; chunk += 256) {
        int p = chunk + threadIdx.x;                    // downsampled pixel index
        int lv = lab[(p >> 8) * 4096 + (p & 255) * 4];  // label[n, 4*i, 4*j]
        bool m = (lv == k);
        unsigned bal = __ballot_sync(0xffffffffu, m);
        int lane = threadIdx.x & 31, wid = threadIdx.x >> 5;
        int rank = __popc(bal & ((1u << lane) - 1));
        if (lane == 0) warp_cnt[wid] = __popc(bal);
        __syncthreads();
        int off = 0, total = 0;
#pragma unroll
        for (int w = 0; w < 8; w++) {
            int cw = warp_cnt[w];
            if (w < wid) off += cw;
            total += cw;
        }
        int base = s_count;
        int pos = base + off + rank;
        if (m && pos < VV) g_idx[b * VV + pos] = p;
        __syncthreads();
        if (threadIdx.x == 0) s_count = base + total;
        __syncthreads();
        if (base + total >= VV) break;                  // uniform across block
    }
}

// One block per output row: gather the 256-dim feature vector for its pixel
// and L2-normalize (matching F.normalize semantics: / max(||x||, 1e-12)).
__global__ void gather_kernel(const float* __restrict__ features) {
    int m = blockIdx.x;
    int t = m / VV, v = m - t * VV;
    int n = t / KC;
    int pix = g_idx[t * VV + v];
    int c = threadIdx.x;
    float val = features[((size_t)(n * CC + c)) * PP + pix];
    float ss = val * val;
#pragma unroll
    for (int o = 16; o; o >>= 1) ss += __shfl_xor_sync(0xffffffffu, ss, o);
    __shared__ float ws[8];
    if ((c & 31) == 0) ws[c >> 5] = ss;
    __syncthreads();
    float s = 0.0f;
#pragma unroll
    for (int w = 0; w < 8; w++) s += ws[w];
    float inv = 1.0f / fmaxf(sqrtf(s), 1e-12f);
    g_F[(size_t)m * CC + c] = val * inv;
}

// Symmetric Gram kernel: 128x128 tile per block, 8x8 per thread, block-upper
// triangle only. Off-diagonal tiles commit both (i,j) and (j,i):
//   same class  -> g_pos[i][slot_j] and g_pos[j][slot_i]
//   diff class  -> exp(g) into negsum[i] (shuffle+global atomic) and into a
//                  per-column smem accumulator flushed to negsum[j].
__global__ void __launch_bounds__(256, 2) gemm_kernel() {
    __shared__ float As[KK][BT];
    __shared__ float Bs[KK][BT];
    __shared__ float sm_nsj[BT];
    __shared__ int s_ci[BT], s_cj[BT];
    __shared__ int s_sloti[BT], s_slotj[BT];

    // decode upper-triangle tile (bi <= bj) from linear block index
    int L = blockIdx.x;
    int bi = (int)((2.0 * NTB + 1.0 -
                    sqrt((2.0 * NTB + 1.0) * (2.0 * NTB + 1.0) - 8.0 * L)) * 0.5);
    while (bi > 0 && bi * NTB - bi * (bi - 1) / 2 > L) bi--;
    while ((bi + 1) * NTB - (bi + 1) * bi / 2 <= L) bi++;
    int bj = bi + (L - (bi * NTB - bi * (bi - 1) / 2));
    int i0 = bi * BT, j0 = bj * BT;
    bool diagBlk = (bi == bj);

    int tid = threadIdx.x;
    int tx = tid & 15, ty = tid >> 4;

    if (tid < BT) {
        int i = i0 + tid;
        sm_nsj[tid] = 0.0f;
        if (i < MM) {
            int t = i / VV, v = i - t * VV;
            s_ci[tid] = t % KC;
            s_sloti[tid] = (t / KC) * VV + v;
        } else { s_ci[tid] = -1; s_sloti[tid] = 0; }
    } else {
        int jj = tid - BT;
        int j = j0 + jj;
        if (j < MM) {
            int t = j / VV, v = j - t * VV;
            s_cj[jj] = t % KC;
            s_slotj[jj] = (t / KC) * VV + v;
        } else { s_cj[jj] = -2; s_slotj[jj] = 0; }
    }

    float acc[8][8];
#pragma unroll
    for (int a = 0; a < 8; a++)
#pragma unroll
        for (int b = 0; b < 8; b++) acc[a][b] = 0.0f;

    // each thread loads one float4 per array per chunk: row = tid>>1, half = tid&1
    int lrow = tid >> 1, lhalf = (tid & 1) * 4;
    int gi = i0 + lrow, gj = j0 + lrow;
    const float* pA = (gi < MM) ? &g_F[(size_t)gi * CC + lhalf] : 0;
    const float* pB = (gj < MM) ? &g_F[(size_t)gj * CC + lhalf] : 0;

    for (int k0 = 0; k0 < CC; k0 += KK) {
        float4 va = pA ? *(const float4*)(pA + k0) : make_float4(0, 0, 0, 0);
        float4 vb = pB ? *(const float4*)(pB + k0) : make_float4(0, 0, 0, 0);
        __syncthreads();
        As[lhalf + 0][lrow] = va.x; As[lhalf + 1][lrow] = va.y;
        As[lhalf + 2][lrow] = va.z; As[lhalf + 3][lrow] = va.w;
        Bs[lhalf + 0][lrow] = vb.x; Bs[lhalf + 1][lrow] = vb.y;
        Bs[lhalf + 2][lrow] = vb.z; Bs[lhalf + 3][lrow] = vb.w;
        __syncthreads();
#pragma unroll
        for (int kk = 0; kk < KK; kk++) {
            float4 a0 = *(const float4*)&As[kk][ty * 8];
            float4 a1 = *(const float4*)&As[kk][ty * 8 + 4];
            float4 b0 = *(const float4*)&Bs[kk][tx * 8];
            float4 b1 = *(const float4*)&Bs[kk][tx * 8 + 4];
            float a[8] = {a0.x, a0.y, a0.z, a0.w, a1.x, a1.y, a1.z, a1.w};
            float b[8] = {b0.x, b0.y, b0.z, b0.w, b1.x, b1.y, b1.z, b1.w};
#pragma unroll
            for (int x = 0; x < 8; x++)
#pragma unroll
                for (int y = 0; y < 8; y++) acc[x][y] += a[x] * b[y];
        }
    }

    // ---- epilogue ----
    float ns_i[8] = {0, 0, 0, 0, 0, 0, 0, 0};
    float ns_j[8] = {0, 0, 0, 0, 0, 0, 0, 0};
#pragma unroll
    for (int a = 0; a < 8; a++) {
        int irow = ty * 8 + a;
        int i = i0 + irow;
        if (i >= MM) continue;
        int ci = s_ci[irow];
#pragma unroll
        for (int b = 0; b < 8; b++) {
            int jj = tx * 8 + b;
            int j = j0 + jj;
            if (j >= MM) continue;
            float g = 2.0f * acc[a][b];   // / TEMPERATURE = 0.5
            if (ci == s_cj[jj]) {
                g_pos[(size_t)i * POS + s_slotj[jj]] = g;
                if (!diagBlk)
                    g_pos[(size_t)j * POS + s_sloti[irow]] = g;
            } else {
                float e = __expf(g);
                ns_i[a] += e;
                if (!diagBlk) ns_j[b] += e;
            }
        }
    }
    // row-side: reduce across the 16 tx lanes (fixed ty = fixed half-warp)
#pragma unroll
    for (int a = 0; a < 8; a++) {
        float vsum = ns_i[a];
#pragma unroll
        for (int o = 8; o; o >>= 1) vsum += __shfl_down_sync(0xffffffffu, vsum, o, 16);
        if (tx == 0) {
            int i = i0 + ty * 8 + a;
            if (i < MM && vsum != 0.0f) atomicAdd(&g_negsum[i], vsum);
        }
    }
    // col-side: accumulate into smem, flush once
    if (!diagBlk) {
#pragma unroll
        for (int b = 0; b < 8; b++) {
            if (ns_j[b] != 0.0f) atomicAdd(&sm_nsj[tx * 8 + b], ns_j[b]);
        }
        __syncthreads();
        if (tid < BT) {
            int j = j0 + tid;
            float v = sm_nsj[tid];
            if (j < MM && v != 0.0f) atomicAdd(&g_negsum[j], v);
        }
    }
}

// Per-row pass over the 524 positive logits:
//   mean over j!=i of (L - log(exp(L) + negsum[i])), divided by 523.
__global__ void row_loss_kernel() {
    int i = blockIdx.x;
    int t = i / VV, v = i - t * VV;
    int diag = (t / KC) * VV + v;
    float nsv = g_negsum[i];
    float lsum = 0.0f;
    for (int s = threadIdx.x; s < POS; s += blockDim.x) {
        if (s == diag) continue;
        float L = g_pos[(size_t)i * POS + s];
        lsum += L - __logf(__expf(L) + nsv);
    }
#pragma unroll
    for (int o = 16; o; o >>= 1) lsum += __shfl_xor_sync(0xffffffffu, lsum, o);
    __shared__ float ws[8];
    if ((threadIdx.x & 31) == 0) ws[threadIdx.x >> 5] = lsum;
    __syncthreads();
    if (threadIdx.x == 0) {
        float s = 0.0f;
#pragma unroll
        for (int w = 0; w < 8; w++) s += ws[w];
        atomicAdd(&g_acc, (double)(s / 523.0f));
    }
}

__global__ void final_kernel(float* __restrict__ out) {
    out[0] = (float)(-g_acc / (double)MM);
}

extern "C" void kernel_launch(void* const* d_in, const int* in_sizes, int n_in,
                              void* d_out, int out_size) {
    const int* label;
    const float* features;
    // label has 4*1024*1024 = 4194304 elements; features 4*256*65536 = 67108864.
    if (in_sizes[0] == 4 * 1024 * 1024) {
        label = (const int*)d_in[0];
        features = (const float*)d_in[1];
    } else {
        label = (const int*)d_in[1];
        features = (const float*)d_in[0];
    }

    init_kernel<<<(MM + 1023) / 1024, 1024>>>();
    select_kernel<<<TT, 256>>>(label);
    gather_kernel<<<MM, 256>>>(features);
    gemm_kernel<<<NBLK, 256>>>();
    row_loss_kernel<<<MM, 256>>>();
    final_kernel<<<1, 1>>>((float*)d_out);
}

// round 16
// speedup vs baseline: 3.3805x; 1.0007x over previous
#include <cuda_runtime.h>
#include <math.h>

// Problem constants (fixed shapes from reference):
//   label    [4,1024,1024] int32, features [4,256,256,256] fp32
#define NN   4
#define KC   19
#define PP   65536          // 256*256 downsampled pixels per image
#define VV   131            // 10000 / 76
#define TT   (NN*KC)        // 76
#define MM   (TT*VV)        // 9956 total feature rows
#define CC   256
#define POS  (NN*VV)        // 524 same-class rows (incl. self)

#define BT   128                         // block tile (i and j)
#define NTB  ((MM + BT - 1) / BT)        // 78
#define NBLK (NTB * (NTB + 1) / 2)       // 3081 upper-triangle tiles
#define KK   8                           // k-chunk

// Static scratch (no allocations allowed). Fully rewritten every launch.
__device__ int    g_idx[TT * VV];       // selected pixel per (t, v)
__device__ float  g_F[MM * CC];         // normalized features, row-major
__device__ float  g_pos[(size_t)MM * POS]; // positive logits per row
__device__ float  g_negsum[MM];         // sum exp(logit) over different-class cols
__device__ double g_acc;                // loss accumulator

__global__ void init_kernel() {
    int i = blockIdx.x * blockDim.x + threadIdx.x;
    if (i < MM) g_negsum[i] = 0.0f;
    if (i == 0) g_acc = 0.0;
}

// One block per (image, class): ordered compaction of the first VV pixels
// (raster order over the ::4,::4 downsample) whose label == class.
__global__ void select_kernel(const int* __restrict__ label) {
    int b = blockIdx.x;
    int n = b / KC, k = b % KC;
    const int* lab = label + (size_t)n * 1024 * 1024;
    __shared__ int s_count;
    __shared__ int warp_cnt[8];
    if (threadIdx.x == 0) s_count = 0;
    __syncthreads();
    for (int chunk = 0; chunk < PP; chunk += 256) {
        int p = chunk + threadIdx.x;                    // downsampled pixel index
        int lv = lab[(p >> 8) * 4096 + (p & 255) * 4];  // label[n, 4*i, 4*j]
        bool m = (lv == k);
        unsigned bal = __ballot_sync(0xffffffffu, m);
        int lane = threadIdx.x & 31, wid = threadIdx.x >> 5;
        int rank = __popc(bal & ((1u << lane) - 1));
        if (lane == 0) warp_cnt[wid] = __popc(bal);
        __syncthreads();
        int off = 0, total = 0;
#pragma unroll
        for (int w = 0; w < 8; w++) {
            int cw = warp_cnt[w];
            if (w < wid) off += cw;
            total += cw;
        }
        int base = s_count;
        int pos = base + off + rank;
        if (m && pos < VV) g_idx[b * VV + pos] = p;
        __syncthreads();
        if (threadIdx.x == 0) s_count = base + total;
        __syncthreads();
        if (base + total >= VV) break;                  // uniform across block
    }
}

// One block per output row: gather the 256-dim feature vector for its pixel
// and L2-normalize (matching F.normalize semantics: / max(||x||, 1e-12)).
__global__ void gather_kernel(const float* __restrict__ features) {
    int m = blockIdx.x;
    int t = m / VV, v = m - t * VV;
    int n = t / KC;
    int pix = g_idx[t * VV + v];
    int c = threadIdx.x;
    float val = features[((size_t)(n * CC + c)) * PP + pix];
    float ss = val * val;
#pragma unroll
    for (int o = 16; o; o >>= 1) ss += __shfl_xor_sync(0xffffffffu, ss, o);
    __shared__ float ws[8];
    if ((c & 31) == 0) ws[c >> 5] = ss;
    __syncthreads();
    float s = 0.0f;
#pragma unroll
    for (int w = 0; w < 8; w++) s += ws[w];
    float inv = 1.0f / fmaxf(sqrtf(s), 1e-12f);
    g_F[(size_t)m * CC + c] = val * inv;
}

// Symmetric Gram kernel: 128x128 tile per block, 8x8 per thread, block-upper
// triangle only. Off-diagonal tiles commit both (i,j) and (j,i):
//   same class  -> g_pos[i][slot_j] and g_pos[j][slot_i]
//   diff class  -> exp(g) into negsum[i] (shuffle+global atomic) and into a
//                  per-column smem accumulator flushed to negsum[j].
__global__ void __launch_bounds__(256, 2) gemm_kernel() {
    __shared__ float As[KK][BT];
    __shared__ float Bs[KK][BT];
    __shared__ float sm_nsj[BT];
    __shared__ int s_ci[BT], s_cj[BT];
    __shared__ int s_sloti[BT], s_slotj[BT];

    // decode upper-triangle tile (bi <= bj) from linear block index
    int L = blockIdx.x;
    int bi = (int)((2.0 * NTB + 1.0 -
                    sqrt((2.0 * NTB + 1.0) * (2.0 * NTB + 1.0) - 8.0 * L)) * 0.5);
    while (bi > 0 && bi * NTB - bi * (bi - 1) / 2 > L) bi--;
    while ((bi + 1) * NTB - (bi + 1) * bi / 2 <= L) bi++;
    int bj = bi + (L - (bi * NTB - bi * (bi - 1) / 2));
    int i0 = bi * BT, j0 = bj * BT;
    bool diagBlk = (bi == bj);

    int tid = threadIdx.x;
    int tx = tid & 15, ty = tid >> 4;

    if (tid < BT) {
        int i = i0 + tid;
        sm_nsj[tid] = 0.0f;
        if (i < MM) {
            int t = i / VV, v = i - t * VV;
            s_ci[tid] = t % KC;
            s_sloti[tid] = (t / KC) * VV + v;
        } else { s_ci[tid] = -1; s_sloti[tid] = 0; }
    } else {
        int jj = tid - BT;
        int j = j0 + jj;
        if (j < MM) {
            int t = j / VV, v = j - t * VV;
            s_cj[jj] = t % KC;
            s_slotj[jj] = (t / KC) * VV + v;
        } else { s_cj[jj] = -2; s_slotj[jj] = 0; }
    }

    float acc[8][8];
#pragma unroll
    for (int a = 0; a < 8; a++)
#pragma unroll
        for (int b = 0; b < 8; b++) acc[a][b] = 0.0f;

    // each thread loads one float4 per array per chunk: row = tid>>1, half = tid&1
    int lrow = tid >> 1, lhalf = (tid & 1) * 4;
    int gi = i0 + lrow, gj = j0 + lrow;
    const float* pA = (gi < MM) ? &g_F[(size_t)gi * CC + lhalf] : 0;
    const float* pB = (gj < MM) ? &g_F[(size_t)gj * CC + lhalf] : 0;

    for (int k0 = 0; k0 < CC; k0 += KK) {
        float4 va = pA ? *(const float4*)(pA + k0) : make_float4(0, 0, 0, 0);
        float4 vb = pB ? *(const float4*)(pB + k0) : make_float4(0, 0, 0, 0);
        __syncthreads();
        As[lhalf + 0][lrow] = va.x; As[lhalf + 1][lrow] = va.y;
        As[lhalf + 2][lrow] = va.z; As[lhalf + 3][lrow] = va.w;
        Bs[lhalf + 0][lrow] = vb.x; Bs[lhalf + 1][lrow] = vb.y;
        Bs[lhalf + 2][lrow] = vb.z; Bs[lhalf + 3][lrow] = vb.w;
        __syncthreads();
#pragma unroll
        for (int kk = 0; kk < KK; kk++) {
            float4 a0 = *(const float4*)&As[kk][ty * 8];
            float4 a1 = *(const float4*)&As[kk][ty * 8 + 4];
            float4 b0 = *(const float4*)&Bs[kk][tx * 8];
            float4 b1 = *(const float4*)&Bs[kk][tx * 8 + 4];
            float a[8] = {a0.x, a0.y, a0.z, a0.w, a1.x, a1.y, a1.z, a1.w};
            float b[8] = {b0.x, b0.y, b0.z, b0.w, b1.x, b1.y, b1.z, b1.w};
#pragma unroll
            for (int x = 0; x < 8; x++)
#pragma unroll
                for (int y = 0; y < 8; y++) acc[x][y] += a[x] * b[y];
        }
    }

    // ---- epilogue ----
    float ns_i[8] = {0, 0, 0, 0, 0, 0, 0, 0};
    float ns_j[8] = {0, 0, 0, 0, 0, 0, 0, 0};
#pragma unroll
    for (int a = 0; a < 8; a++) {
        int irow = ty * 8 + a;
        int i = i0 + irow;
        if (i >= MM) continue;
        int ci = s_ci[irow];
#pragma unroll
        for (int b = 0; b < 8; b++) {
            int jj = tx * 8 + b;
            int j = j0 + jj;
            if (j >= MM) continue;
            float g = 2.0f * acc[a][b];   // / TEMPERATURE = 0.5
            if (ci == s_cj[jj]) {
                g_pos[(size_t)i * POS + s_slotj[jj]] = g;
                if (!diagBlk)
                    g_pos[(size_t)j * POS + s_sloti[irow]] = g;
            } else {
                float e = __expf(g);
                ns_i[a] += e;
                if (!diagBlk) ns_j[b] += e;
            }
        }
    }
    // row-side: reduce across the 16 tx lanes (fixed ty = fixed half-warp)
#pragma unroll
    for (int a = 0; a < 8; a++) {
        float vsum = ns_i[a];
#pragma unroll
        for (int o = 8; o; o >>= 1) vsum += __shfl_down_sync(0xffffffffu, vsum, o, 16);
        if (tx == 0) {
            int i = i0 + ty * 8 + a;
            if (i < MM && vsum != 0.0f) atomicAdd(&g_negsum[i], vsum);
        }
    }
    // col-side: accumulate into smem, flush once
    if (!diagBlk) {
#pragma unroll
        for (int b = 0; b < 8; b++) {
            if (ns_j[b] != 0.0f) atomicAdd(&sm_nsj[tx * 8 + b], ns_j[b]);
        }
        __syncthreads();
        if (tid < BT) {
            int j = j0 + tid;
            float v = sm_nsj[tid];
            if (j < MM && v != 0.0f) atomicAdd(&g_negsum[j], v);
        }
    }
}

// Per-row pass over the 524 positive logits:
//   mean over j!=i of (L - log(exp(L) + negsum[i])), divided by 523.
__global__ void row_loss_kernel() {
    int i = blockIdx.x;
    int t = i / VV, v = i - t * VV;
    int diag = (t / KC) * VV + v;
    float nsv = g_negsum[i];
    float lsum = 0.0f;
    for (int s = threadIdx.x; s < POS; s += blockDim.x) {
        if (s == diag) continue;
        float L = g_pos[(size_t)i * POS + s];
        lsum += L - __logf(__expf(L) + nsv);
    }
#pragma unroll
    for (int o = 16; o; o >>= 1) lsum += __shfl_xor_sync(0xffffffffu, lsum, o);
    __shared__ float ws[8];
    if ((threadIdx.x & 31) == 0) ws[threadIdx.x >> 5] = lsum;
    __syncthreads();
    if (threadIdx.x == 0) {
        float s = 0.0f;
#pragma unroll
        for (int w = 0; w < 8; w++) s += ws[w];
        atomicAdd(&g_acc, (double)(s / 523.0f));
    }
}

__global__ void final_kernel(float* __restrict__ out) {
    out[0] = (float)(-g_acc / (double)MM);
}

extern "C" void kernel_launch(void* const* d_in, const int* in_sizes, int n_in,
                              void* d_out, int out_size) {
    const int* label;
    const float* features;
    // label has 4*1024*1024 = 4194304 elements; features 4*256*65536 = 67108864.
    if (in_sizes[0] == 4 * 1024 * 1024) {
        label = (const int*)d_in[0];
        features = (const float*)d_in[1];
    } else {
        label = (const int*)d_in[1];
        features = (const float*)d_in[0];
    }

    init_kernel<<<(MM + 1023) / 1024, 1024>>>();
    select_kernel<<<TT, 256>>>(label);
    gather_kernel<<<MM, 256>>>(features);
    gemm_kernel<<<NBLK, 256>>>();
    row_loss_kernel<<<MM, 256>>>();
    final_kernel<<<1, 1>>>((float*)d_out);
}